// round 15
// baseline (speedup 1.0000x reference)
#include <cuda_runtime.h>
#include <cuda_bf16.h>

// y[b,c,h,w] = coef[c] * g[b,c,h,w]
// g: (32, 512, 64, 64) fp32, coef: (512,) fp32.
//
// Base = best-of-8 measured config (harness 81.92us, reproduced twice):
//   one block = 256 threads x 4 float4 = one 4096-float (b,c) channel plane;
//   grid 16384; block-uniform coef (c = blockIdx.x & 511); ILP=4 front-
//   batched LDG.128.cs (MLP=4/thread); 4x STG.128.
//
// This round's single delta: stores use write-through (__stwt / st.global.wt)
// instead of .cs evict-first. Pure streaming 256 MiB write with no read-back:
// WT skips the L2 dirty-line allocate/writeback lifecycle, pushing store data
// straight toward DRAM and smoothing the read/write interleave at the
// memory controller.

__global__ __launch_bounds__(256)
void Gradient_28733331210651_kernel(const float4* __restrict__ g4,
                                    const float* __restrict__ coef,
                                    float4* __restrict__ out4) {
    // Block-uniform channel + scale
    const int c = blockIdx.x & 511;
    const float s = __ldg(coef + c);

    const long long base = (long long)blockIdx.x * 1024 + threadIdx.x;

    // Front-batched streaming loads (MLP=4)
    float4 v0 = __ldcs(g4 + base);
    float4 v1 = __ldcs(g4 + base + 256);
    float4 v2 = __ldcs(g4 + base + 512);
    float4 v3 = __ldcs(g4 + base + 768);

    v0.x *= s; v0.y *= s; v0.z *= s; v0.w *= s;
    v1.x *= s; v1.y *= s; v1.z *= s; v1.w *= s;
    v2.x *= s; v2.y *= s; v2.z *= s; v2.w *= s;
    v3.x *= s; v3.y *= s; v3.z *= s; v3.w *= s;

    // Write-through stores
    __stwt(out4 + base,       v0);
    __stwt(out4 + base + 256, v1);
    __stwt(out4 + base + 512, v2);
    __stwt(out4 + base + 768, v3);
}

extern "C" void kernel_launch(void* const* d_in, const int* in_sizes, int n_in,
                              void* d_out, int out_size) {
    const float4* g4   = (const float4*)d_in[0];
    const float*  coef = (const float*)d_in[1];
    float4*       out4 = (float4*)d_out;

    // 32*512*64*64 floats; one block per 4096-float channel plane
    long long n  = (long long)in_sizes[0];      // 67108864
    long long blocks = n >> 12;                 // 16384

    Gradient_28733331210651_kernel<<<(unsigned)blocks, 256>>>(g4, coef, out4);
}